// round 11
// baseline (speedup 1.0000x reference)
#include <cuda_runtime.h>
#include <cuda_bf16.h>
#include <math.h>

// Problem dims
#define B_   128
#define T_   512
#define E_   256
#define H_   512
#define G3   1536   // 3H per direction
#define GT   3072   // both directions stacked

// Recurrence decomposition: 2 dirs x 12 mtiles(128 gate rows) x 4 kchunks(128 k)
#define NDIR       2
#define NMT        12
#define NKC        4
#define CTAS_DIR   (NMT * NKC)          // 48
#define NCTA_REC   (NDIR * CTAS_DIR)    // 96
#define REC_THREADS 256

// ---------------- scratch (device globals; no allocation allowed) ----------------
__device__ float g_xpT[(size_t)T_ * GT * B_];              // xpT[t][g][b]
__device__ float g_P[(size_t)NDIR * NMT * NKC * 128 * B_]; // partial D tiles
__device__ __nv_bfloat16 g_hh[NDIR * B_ * H_];             // h hi  [dir][b][j]
__device__ __nv_bfloat16 g_hl[NDIR * B_ * H_];             // h lo  [dir][b][j]
__device__ float g_hf[NDIR * H_ * B_];                     // h fp32 [dir][j][b]
__device__ unsigned g_bc[NDIR];
__device__ unsigned g_bg[NDIR];
__device__ unsigned g_ibc;
__device__ unsigned g_ibg;

// ---------------- PTX helpers ----------------
__device__ __forceinline__ unsigned smem_u32(const void* p) {
    unsigned a;
    asm("{ .reg .u64 t; cvta.to.shared.u64 t, %1; cvt.u32.u64 %0, t; }" : "=r"(a) : "l"(p));
    return a;
}
__device__ __forceinline__ void ldsm4(unsigned* r, unsigned addr) {
    asm volatile("ldmatrix.sync.aligned.m8n8.x4.shared.b16 {%0,%1,%2,%3}, [%4];"
        : "=r"(r[0]), "=r"(r[1]), "=r"(r[2]), "=r"(r[3]) : "r"(addr));
}
__device__ __forceinline__ void mma16816(float* d, const unsigned* a,
                                         unsigned b0, unsigned b1) {
    asm volatile(
        "mma.sync.aligned.m16n8k16.row.col.f32.bf16.bf16.f32 "
        "{%0,%1,%2,%3}, {%4,%5,%6,%7}, {%8,%9}, {%0,%1,%2,%3};"
        : "+f"(d[0]), "+f"(d[1]), "+f"(d[2]), "+f"(d[3])
        : "r"(a[0]), "r"(a[1]), "r"(a[2]), "r"(a[3]), "r"(b0), "r"(b1));
}
// swizzled byte offset within a [128 rows x 128 bf16] tile (256B rows)
__device__ __forceinline__ int sw_off(int row, int kbyte) {
    return row * 256 + (kbyte ^ ((row & 7) << 4));
}

// =================================================================================
// Phase 1: input projection GEMM (scalar fp32 — measured 2.39ms in R3)
// =================================================================================
__global__ void __launch_bounds__(256) proj_kernel(
    const int* __restrict__ inputs, const float* __restrict__ emb,
    const float* __restrict__ Wf, const float* __restrict__ Wb,
    const float* __restrict__ bf, const float* __restrict__ bb)
{
    __shared__ float As[16][128];
    __shared__ float Bs[16][128];
    __shared__ int   toks[128];

    const int t   = blockIdx.x;
    const int g0  = blockIdx.y * 128;
    const int tid = threadIdx.x;

    if (tid < 128) toks[tid] = inputs[tid * T_ + t];
    __syncthreads();

    const int    isB  = (g0 >= G3);
    const float* W    = isB ? Wb : Wf;
    const float* bias = isB ? bb : bf;
    const int    gl0  = g0 - (isB ? G3 : 0);

    const int tx = tid & 15;
    const int ty = tid >> 4;

    float acc[8][8];
    #pragma unroll
    for (int i = 0; i < 8; i++)
        #pragma unroll
        for (int j = 0; j < 8; j++) acc[i][j] = 0.f;

    for (int k0 = 0; k0 < E_; k0 += 16) {
        #pragma unroll
        for (int l = 0; l < 2; l++) {
            int idx = tid * 2 + l;
            int row = idx >> 2, q = idx & 3;
            float4 v = *reinterpret_cast<const float4*>(
                &W[(size_t)(gl0 + row) * E_ + k0 + q * 4]);
            As[q*4+0][row] = v.x; As[q*4+1][row] = v.y;
            As[q*4+2][row] = v.z; As[q*4+3][row] = v.w;
        }
        #pragma unroll
        for (int l = 0; l < 2; l++) {
            int idx = tid * 2 + l;
            int b = idx >> 2, q = idx & 3;
            float4 v = *reinterpret_cast<const float4*>(
                &emb[(size_t)toks[b] * E_ + k0 + q * 4]);
            Bs[q*4+0][b] = v.x; Bs[q*4+1][b] = v.y;
            Bs[q*4+2][b] = v.z; Bs[q*4+3][b] = v.w;
        }
        __syncthreads();

        #pragma unroll
        for (int k = 0; k < 16; k++) {
            float af[8], bfr[8];
            #pragma unroll
            for (int i = 0; i < 8; i++) af[i]  = As[k][ty*8 + i];
            #pragma unroll
            for (int i = 0; i < 8; i++) bfr[i] = Bs[k][tx*8 + i];
            #pragma unroll
            for (int i = 0; i < 8; i++)
                #pragma unroll
                for (int j = 0; j < 8; j++)
                    acc[i][j] = fmaf(af[i], bfr[j], acc[i][j]);
        }
        __syncthreads();
    }

    #pragma unroll
    for (int i = 0; i < 8; i++) {
        int g = g0 + ty*8 + i;
        float bv = bias[gl0 + ty*8 + i];
        float* dst = &g_xpT[((size_t)t * GT + g) * B_ + tx*8];
        *reinterpret_cast<float4*>(dst) =
            make_float4(acc[i][0]+bv, acc[i][1]+bv, acc[i][2]+bv, acc[i][3]+bv);
        *reinterpret_cast<float4*>(dst+4) =
            make_float4(acc[i][4]+bv, acc[i][5]+bv, acc[i][6]+bv, acc[i][7]+bv);
    }
}

// =================================================================================
// per-domain software barrier
// =================================================================================
__device__ __forceinline__ void sw_barrier(unsigned* cnt, unsigned* gen, unsigned n) {
    __syncthreads();
    if (threadIdx.x == 0) {
        volatile unsigned* gp = gen;
        unsigned old = *gp;
        __threadfence();
        if (atomicAdd(cnt, 1u) == n - 1) {
            atomicExch(cnt, 0u);
            __threadfence();
            *gp = old + 1;
        } else {
            while (*gp == old) { __nanosleep(20); }
        }
    }
    __syncthreads();
}

// =================================================================================
// Phase 2: persistent recurrence, HMMA (mma.sync bf16-split) phase A.
// CTA (dir, mtile, kc): D[128g x 128b] = Whi*Hhi + Whi*Hlo + Wlo*Hhi over K=128.
// =================================================================================
#define SO_WHI  0
#define SO_WLO  32768
#define SO_HHI  65536
#define SO_HLO  98304
#define SO_END  131072

__global__ void __launch_bounds__(REC_THREADS, 1) rec_kernel(
    const float* __restrict__ Whf, const float* __restrict__ Whb,
    const float* __restrict__ bhf, const float* __restrict__ bhb)
{
    extern __shared__ char smem[];
    const unsigned sb = smem_u32(smem);
    const int tid  = threadIdx.x;
    const int wid  = tid >> 5;
    const int lane = tid & 31;

    const int cta   = blockIdx.x;          // 0..95
    const int dir   = cta / CTAS_DIR;
    const int c48   = cta % CTAS_DIR;
    const int mtile = c48 >> 2;            // 0..11
    const int kc    = c48 & 3;             // 0..3
    const float* Wh = dir ? Whb : Whf;
    const float* bh = dir ? bhb : bhf;

    // One-time: W chunk -> SMEM swizzled bf16 hi/lo
    for (int i = tid; i < 128*128; i += REC_THREADS) {
        int r = i >> 7, k = i & 127;
        float w = Wh[(size_t)(mtile*128 + r) * H_ + kc*128 + k];
        __nv_bfloat16 hi = __float2bfloat16(w);
        __nv_bfloat16 lo = __float2bfloat16(w - __bfloat162float(hi));
        int off = sw_off(r, k * 2);
        *reinterpret_cast<__nv_bfloat16*>(smem + SO_WHI + off) = hi;
        *reinterpret_cast<__nv_bfloat16*>(smem + SO_WLO + off) = lo;
    }

    // Zero hidden state (grid-strided)
    {
        const int gt = cta * REC_THREADS + tid;
        const int nthr = NCTA_REC * REC_THREADS;
        unsigned long long* hh4 = reinterpret_cast<unsigned long long*>(g_hh);
        unsigned long long* hl4 = reinterpret_cast<unsigned long long*>(g_hl);
        for (int i = gt; i < NDIR*B_*H_/4; i += nthr) { hh4[i] = 0ull; hl4[i] = 0ull; }
        for (int i = gt; i < NDIR*H_*B_; i += nthr) g_hf[i] = 0.f;
    }
    __threadfence();
    // one-time all-CTA barrier
    __syncthreads();
    if (tid == 0) {
        volatile unsigned* gp = &g_ibg;
        unsigned old = *gp;
        __threadfence();
        if (atomicAdd(&g_ibc, 1u) == NCTA_REC - 1) {
            atomicExch(&g_ibc, 0u); __threadfence(); *gp = old + 1;
        } else { while (*gp == old) { __nanosleep(20); } }
    }
    __syncthreads();

    // ldmatrix per-lane invariants
    const int lrow = lane & 15;        // row within 16-row ldmatrix tile
    const int lkb  = (lane >> 4) * 16; // k byte offset (8 bf16)
    // A (W) addresses: row = wid*16 + lrow
    const int arow  = wid * 16 + lrow;
    const unsigned a_hi_base = sb + SO_WHI + arow * 256;
    const unsigned a_lo_base = sb + SO_WLO + arow * 256;
    const int a_xor = (arow & 7) << 4;

    const int pb_b  = tid & 127;
    const int pb_sl = tid >> 7;

    for (int t = 0; t < T_; t++) {
        // ---- stage h chunk [128 b x 128 k] hi/lo into swizzled SMEM
        for (int i = tid; i < 2048; i += REC_THREADS) {
            int b = i >> 4, kq = i & 15;
            size_t gidx = ((size_t)(dir*B_ + b) * H_) + kc*128 + kq*8;
            uint4 vh = __ldcg(reinterpret_cast<const uint4*>(&g_hh[gidx]));
            uint4 vl = __ldcg(reinterpret_cast<const uint4*>(&g_hl[gidx]));
            int off = sw_off(b, kq * 16);
            *reinterpret_cast<uint4*>(smem + SO_HHI + off) = vh;
            *reinterpret_cast<uint4*>(smem + SO_HLO + off) = vl;
        }
        __syncthreads();

        // ---- HMMA mainloop: warp owns g rows [wid*16, wid*16+16), all 128 b
        float d[16][4];
        #pragma unroll
        for (int nb = 0; nb < 16; nb++)
            #pragma unroll
            for (int q = 0; q < 4; q++) d[nb][q] = 0.f;

        for (int ks = 0; ks < 8; ks++) {
            unsigned ahi[4], alo[4];
            int akb = (ks * 32 + lkb) ^ a_xor;   // k byte (ks*16 bf16 = 32B)
            ldsm4(ahi, a_hi_base + akb);
            ldsm4(alo, a_lo_base + akb);

            #pragma unroll
            for (int nbp = 0; nbp < 8; nbp++) {
                int brow = nbp * 16 + lrow;
                int boff = brow * 256 + ((ks * 32 + lkb) ^ ((brow & 7) << 4));
                unsigned bhi4[4], blo4[4];
                ldsm4(bhi4, sb + SO_HHI + boff);
                ldsm4(blo4, sb + SO_HLO + boff);
                // hi*hi
                mma16816(d[2*nbp],   ahi, bhi4[0], bhi4[2]);
                mma16816(d[2*nbp+1], ahi, bhi4[1], bhi4[3]);
                // hi*lo
                mma16816(d[2*nbp],   ahi, blo4[0], blo4[2]);
                mma16816(d[2*nbp+1], ahi, blo4[1], blo4[3]);
                // lo*hi
                mma16816(d[2*nbp],   alo, bhi4[0], bhi4[2]);
                mma16816(d[2*nbp+1], alo, bhi4[1], bhi4[3]);
            }
        }

        // ---- epilogue: write D fragments to g_P[dir][mt][kc][g][b]
        {
            const int g0r = wid * 16 + (lane >> 2);       // rows g0r and g0r+8
            const int c0  = (lane & 3) * 2;
            float* base = &g_P[(((size_t)(dir*NMT + mtile)*NKC + kc)*128) * B_];
            #pragma unroll
            for (int nb = 0; nb < 16; nb++) {
                int col = nb * 8 + c0;
                __stcg(reinterpret_cast<float2*>(base + (size_t)g0r * B_ + col),
                       make_float2(d[nb][0], d[nb][1]));
                __stcg(reinterpret_cast<float2*>(base + (size_t)(g0r + 8) * B_ + col),
                       make_float2(d[nb][2], d[nb][3]));
            }
        }
        __threadfence();
        sw_barrier(&g_bc[dir], &g_bg[dir], CTAS_DIR);

        // ---- phase B: gating. First 32 CTAs of this dir own 16 units each.
        if (c48 < 32) {
            const int te = dir ? (T_ - 1 - t) : t;
            #pragma unroll
            for (int q = 0; q < 8; q++) {
                int unit = c48*16 + pb_sl*8 + q;
                float hg[3], xg[3];
                #pragma unroll
                for (int gate = 0; gate < 3; gate++) {
                    int g  = gate*H_ + unit;
                    int mt = g >> 7, ln = g & 127;
                    float s = bh[g];
                    #pragma unroll
                    for (int c = 0; c < NKC; c++)
                        s += __ldcg(&g_P[(((size_t)(dir*NMT + mt)*NKC + c)*128 + ln) * B_ + pb_b]);
                    hg[gate] = s;
                    xg[gate] = __ldcg(&g_xpT[((size_t)te * GT + dir*G3 + g) * B_ + pb_b]);
                }
                float r = 1.f / (1.f + __expf(-(xg[0] + hg[0])));
                float z = 1.f / (1.f + __expf(-(xg[1] + hg[1])));
                float n = tanhf(xg[2] + r * hg[2]);
                float* hfp = &g_hf[(dir*H_ + unit) * B_ + pb_b];
                float ho = *hfp;
                float hnew = (1.f - z) * n + z * ho;
                *hfp = hnew;
                __nv_bfloat16 hi = __float2bfloat16(hnew);
                __nv_bfloat16 lo = __float2bfloat16(hnew - __bfloat162float(hi));
                size_t hidx = ((size_t)(dir*B_ + pb_b) * H_) + unit;
                g_hh[hidx] = hi;
                g_hl[hidx] = lo;
            }
        }
        __threadfence();
        sw_barrier(&g_bc[dir], &g_bg[dir], CTAS_DIR);
    }
}

// =================================================================================
// Phase 3: final FC + sigmoid
// =================================================================================
__global__ void fc_kernel(const float* __restrict__ fcw,
                          const float* __restrict__ fcb,
                          float* __restrict__ out)
{
    int b = threadIdx.x;   // 128 threads
    float s = 0.f;
    for (int j = 0; j < H_; j++)
        s = fmaf(g_hf[(0*H_ + j) * B_ + b], fcw[j], s);
    for (int j = 0; j < H_; j++)
        s = fmaf(g_hf[(1*H_ + j) * B_ + b], fcw[H_ + j], s);
    out[b] = 1.f / (1.f + __expf(-(s + fcb[0])));
}

// =================================================================================
extern "C" void kernel_launch(void* const* d_in, const int* in_sizes, int n_in,
                              void* d_out, int out_size)
{
    const int*   inputs = (const int*)  d_in[0];
    const float* emb    = (const float*)d_in[1];
    const float* Wihf   = (const float*)d_in[2];
    const float* Whhf   = (const float*)d_in[3];
    const float* bihf   = (const float*)d_in[4];
    const float* bhhf   = (const float*)d_in[5];
    const float* Wihb   = (const float*)d_in[6];
    const float* Whhb   = (const float*)d_in[7];
    const float* bihb   = (const float*)d_in[8];
    const float* bhhb   = (const float*)d_in[9];
    const float* fcw    = (const float*)d_in[10];
    const float* fcb    = (const float*)d_in[11];
    float* out = (float*)d_out;

    cudaFuncSetAttribute(rec_kernel,
                         cudaFuncAttributeMaxDynamicSharedMemorySize, SO_END);

    proj_kernel<<<dim3(T_, GT/128), 256>>>(inputs, emb, Wihf, Wihb, bihf, bihb);
    rec_kernel<<<NCTA_REC, REC_THREADS, SO_END>>>(Whhf, Whhb, bhhf, bhhb);
    fc_kernel<<<1, B_>>>(fcw, fcb, out);

    (void)in_sizes; (void)n_in; (void)out_size;
}

// round 12
// speedup vs baseline: 1.2336x; 1.2336x over previous
#include <cuda_runtime.h>
#include <cuda_bf16.h>
#include <math.h>

// Problem dims
#define B_   128
#define T_   512
#define E_   256
#define H_   512
#define G3   1536   // 3H per direction
#define GT   3072   // both directions stacked

// Recurrence decomposition:
//   2 dirs x 6 mtiles (256 gate rows) x 12 slots (4 kchunks x 3 split terms)
#define NDIR       2
#define NMT        6
#define NSLOT      12
#define NKC        4
#define CTAS_DIR   (NMT * NSLOT)        // 72
#define NCTA_REC   (NDIR * CTAS_DIR)    // 144
#define REC_THREADS 512

// ---------------- scratch (device globals; no allocation allowed) ----------------
__device__ float g_xpT[(size_t)T_ * GT * B_];                 // xpT[t][g][b]
__device__ float g_P[(size_t)NDIR * NMT * NSLOT * 256 * B_];  // partial D tiles
__device__ __nv_bfloat16 g_hh[NDIR * B_ * H_];                // h hi  [dir][b][j]
__device__ __nv_bfloat16 g_hl[NDIR * B_ * H_];                // h lo  [dir][b][j]
__device__ float g_hf[NDIR * H_ * B_];                        // h fp32 [dir][j][b]
__device__ unsigned g_bc[NDIR];
__device__ unsigned g_bg[NDIR];
__device__ unsigned g_ibc;
__device__ unsigned g_ibg;

// ---------------- PTX helpers ----------------
__device__ __forceinline__ unsigned smem_u32(const void* p) {
    unsigned a;
    asm("{ .reg .u64 t; cvta.to.shared.u64 t, %1; cvt.u32.u64 %0, t; }" : "=r"(a) : "l"(p));
    return a;
}
__device__ __forceinline__ void ldsm4(unsigned* r, unsigned addr) {
    asm volatile("ldmatrix.sync.aligned.m8n8.x4.shared.b16 {%0,%1,%2,%3}, [%4];"
        : "=r"(r[0]), "=r"(r[1]), "=r"(r[2]), "=r"(r[3]) : "r"(addr));
}
__device__ __forceinline__ void mma16816(float* d, const unsigned* a,
                                         unsigned b0, unsigned b1) {
    asm volatile(
        "mma.sync.aligned.m16n8k16.row.col.f32.bf16.bf16.f32 "
        "{%0,%1,%2,%3}, {%4,%5,%6,%7}, {%8,%9}, {%0,%1,%2,%3};"
        : "+f"(d[0]), "+f"(d[1]), "+f"(d[2]), "+f"(d[3])
        : "r"(a[0]), "r"(a[1]), "r"(a[2]), "r"(a[3]), "r"(b0), "r"(b1));
}
// swizzled byte offset in a tile with 256B rows (128 bf16 per row)
__device__ __forceinline__ int sw_off(int row, int kbyte) {
    return row * 256 + (kbyte ^ ((row & 7) << 4));
}

// =================================================================================
// dummy kernel: shifts ncu's -s 5 -c 1 capture window onto rec_kernel
// =================================================================================
__global__ void dummy_kernel() {}

// =================================================================================
// Phase 1: input projection GEMM (scalar fp32 — measured-good 2.39ms)
// =================================================================================
__global__ void __launch_bounds__(256) proj_kernel(
    const int* __restrict__ inputs, const float* __restrict__ emb,
    const float* __restrict__ Wf, const float* __restrict__ Wb,
    const float* __restrict__ bf, const float* __restrict__ bb)
{
    __shared__ float As[16][128];
    __shared__ float Bs[16][128];
    __shared__ int   toks[128];

    const int t   = blockIdx.x;
    const int g0  = blockIdx.y * 128;
    const int tid = threadIdx.x;

    if (tid < 128) toks[tid] = inputs[tid * T_ + t];
    __syncthreads();

    const int    isB  = (g0 >= G3);
    const float* W    = isB ? Wb : Wf;
    const float* bias = isB ? bb : bf;
    const int    gl0  = g0 - (isB ? G3 : 0);

    const int tx = tid & 15;
    const int ty = tid >> 4;

    float acc[8][8];
    #pragma unroll
    for (int i = 0; i < 8; i++)
        #pragma unroll
        for (int j = 0; j < 8; j++) acc[i][j] = 0.f;

    for (int k0 = 0; k0 < E_; k0 += 16) {
        #pragma unroll
        for (int l = 0; l < 2; l++) {
            int idx = tid * 2 + l;
            int row = idx >> 2, q = idx & 3;
            float4 v = *reinterpret_cast<const float4*>(
                &W[(size_t)(gl0 + row) * E_ + k0 + q * 4]);
            As[q*4+0][row] = v.x; As[q*4+1][row] = v.y;
            As[q*4+2][row] = v.z; As[q*4+3][row] = v.w;
        }
        #pragma unroll
        for (int l = 0; l < 2; l++) {
            int idx = tid * 2 + l;
            int b = idx >> 2, q = idx & 3;
            float4 v = *reinterpret_cast<const float4*>(
                &emb[(size_t)toks[b] * E_ + k0 + q * 4]);
            Bs[q*4+0][b] = v.x; Bs[q*4+1][b] = v.y;
            Bs[q*4+2][b] = v.z; Bs[q*4+3][b] = v.w;
        }
        __syncthreads();

        #pragma unroll
        for (int k = 0; k < 16; k++) {
            float af[8], bfr[8];
            #pragma unroll
            for (int i = 0; i < 8; i++) af[i]  = As[k][ty*8 + i];
            #pragma unroll
            for (int i = 0; i < 8; i++) bfr[i] = Bs[k][tx*8 + i];
            #pragma unroll
            for (int i = 0; i < 8; i++)
                #pragma unroll
                for (int j = 0; j < 8; j++)
                    acc[i][j] = fmaf(af[i], bfr[j], acc[i][j]);
        }
        __syncthreads();
    }

    #pragma unroll
    for (int i = 0; i < 8; i++) {
        int g = g0 + ty*8 + i;
        float bv = bias[gl0 + ty*8 + i];
        float* dst = &g_xpT[((size_t)t * GT + g) * B_ + tx*8];
        *reinterpret_cast<float4*>(dst) =
            make_float4(acc[i][0]+bv, acc[i][1]+bv, acc[i][2]+bv, acc[i][3]+bv);
        *reinterpret_cast<float4*>(dst+4) =
            make_float4(acc[i][4]+bv, acc[i][5]+bv, acc[i][6]+bv, acc[i][7]+bv);
    }
}

// =================================================================================
// per-domain software barrier
// =================================================================================
__device__ __forceinline__ void sw_barrier(unsigned* cnt, unsigned* gen, unsigned n) {
    __syncthreads();
    if (threadIdx.x == 0) {
        volatile unsigned* gp = gen;
        unsigned old = *gp;
        __threadfence();
        if (atomicAdd(cnt, 1u) == n - 1) {
            atomicExch(cnt, 0u);
            __threadfence();
            *gp = old + 1;
        } else {
            while (*gp == old) { __nanosleep(20); }
        }
    }
    __syncthreads();
}

// =================================================================================
// Phase 2: persistent recurrence, HMMA bf16-split with term-per-CTA.
// CTA (dir, mt, slot=term*4+kc): D[256g x 128b] = Wv * Hv over its 128-k chunk,
//   where (Wv,Hv) = term0:(hi,hi) term1:(hi,lo) term2:(lo,hi).
// =================================================================================
#define SO_W   0          // 256 x 128 bf16, swizzled, 64 KB
#define SO_H   65536      // 128 x 128 bf16, swizzled, 32 KB
#define SO_END 98304

__global__ void __launch_bounds__(REC_THREADS, 1) rec_kernel(
    const float* __restrict__ Whf, const float* __restrict__ Whb,
    const float* __restrict__ bhf, const float* __restrict__ bhb)
{
    extern __shared__ char smem[];
    const unsigned sb = smem_u32(smem);
    const int tid  = threadIdx.x;
    const int wid  = tid >> 5;     // 0..15
    const int lane = tid & 31;

    const int cta  = blockIdx.x;        // 0..143
    const int dir  = cta / CTAS_DIR;
    const int c72  = cta % CTAS_DIR;
    const int mt   = c72 / NSLOT;       // 0..5 (256 gate rows each)
    const int slot = c72 % NSLOT;       // 0..11
    const int term = slot >> 2;         // 0..2
    const int kc   = slot & 3;          // 0..3
    const float* Wh = dir ? Whb : Whf;
    const float* bh = dir ? bhb : bhf;

    // One-time: W tile (version per term) -> swizzled SMEM
    for (int i = tid; i < 256*128; i += REC_THREADS) {
        int r = i >> 7, k = i & 127;
        float w = Wh[(size_t)(mt*256 + r) * H_ + kc*128 + k];
        __nv_bfloat16 hi = __float2bfloat16(w);
        __nv_bfloat16 v  = (term == 2)
            ? __float2bfloat16(w - __bfloat162float(hi)) : hi;
        *reinterpret_cast<__nv_bfloat16*>(smem + SO_W + sw_off(r, k*2)) = v;
    }

    // Zero hidden state (grid-strided over all CTAs)
    {
        const int gt = cta * REC_THREADS + tid;
        const int nthr = NCTA_REC * REC_THREADS;
        unsigned long long* hh4 = reinterpret_cast<unsigned long long*>(g_hh);
        unsigned long long* hl4 = reinterpret_cast<unsigned long long*>(g_hl);
        for (int i = gt; i < NDIR*B_*H_/4; i += nthr) { hh4[i] = 0ull; hl4[i] = 0ull; }
        for (int i = gt; i < NDIR*H_*B_; i += nthr) g_hf[i] = 0.f;
    }
    __threadfence();
    // one-time all-CTA barrier
    __syncthreads();
    if (tid == 0) {
        volatile unsigned* gp = &g_ibg;
        unsigned old = *gp;
        __threadfence();
        if (atomicAdd(&g_ibc, 1u) == NCTA_REC - 1) {
            atomicExch(&g_ibc, 0u); __threadfence(); *gp = old + 1;
        } else { while (*gp == old) { __nanosleep(20); } }
    }
    __syncthreads();

    // warp tiling: wm = 32-row group (0..7), wn = 64-col half (0..1)
    const int wm = wid & 7;
    const int wn = wid >> 3;
    const int lrow = lane & 15;
    const int lkb  = (lane >> 4) * 16;   // byte offset within 32B k-slice

    // A (W) ldmatrix bases per m-subtile
    unsigned a_base[2]; int a_xor[2];
    #pragma unroll
    for (int mi = 0; mi < 2; mi++) {
        int arow = wm*32 + mi*16 + lrow;
        a_base[mi] = sb + SO_W + arow * 256;
        a_xor[mi]  = (arow & 7) << 4;
    }
    // B (h) ldmatrix bases per n-subtile (b-columns group of 16)
    unsigned b_base[4]; int b_xor[4];
    #pragma unroll
    for (int nt = 0; nt < 4; nt++) {
        int brow = wn*64 + nt*16 + lrow;
        b_base[nt] = sb + SO_H + brow * 256;
        b_xor[nt]  = (brow & 7) << 4;
    }

    const __nv_bfloat16* hsrc_g = (term == 1) ? g_hl : g_hh;
    const int pb_b   = tid & 127;
    const int pb_sub = tid >> 7;          // 0..3

    for (int t = 0; t < T_; t++) {
        // ---- stage h chunk [128 b x 128 k] (single version) into swizzled SMEM
        for (int i = tid; i < 2048; i += REC_THREADS) {
            int b = i >> 4, kq = i & 15;
            size_t gidx = ((size_t)(dir*B_ + b) * H_) + kc*128 + kq*8;
            uint4 v = __ldcg(reinterpret_cast<const uint4*>(&hsrc_g[gidx]));
            *reinterpret_cast<uint4*>(smem + SO_H + sw_off(b, kq*16)) = v;
        }
        __syncthreads();

        // ---- HMMA mainloop: warp owns 32 g-rows x 64 b-cols
        float d[2][8][4];
        #pragma unroll
        for (int mi = 0; mi < 2; mi++)
            #pragma unroll
            for (int n8 = 0; n8 < 8; n8++)
                #pragma unroll
                for (int q = 0; q < 4; q++) d[mi][n8][q] = 0.f;

        #pragma unroll
        for (int ks = 0; ks < 8; ks++) {
            const int kb = ks * 32 + lkb;
            unsigned a0[4], a1[4];
            ldsm4(a0, a_base[0] + (kb ^ a_xor[0]));
            ldsm4(a1, a_base[1] + (kb ^ a_xor[1]));
            #pragma unroll
            for (int nt = 0; nt < 4; nt++) {
                unsigned bb[4];
                ldsm4(bb, b_base[nt] + (kb ^ b_xor[nt]));
                mma16816(d[0][2*nt],   a0, bb[0], bb[2]);
                mma16816(d[0][2*nt+1], a0, bb[1], bb[3]);
                mma16816(d[1][2*nt],   a1, bb[0], bb[2]);
                mma16816(d[1][2*nt+1], a1, bb[1], bb[3]);
            }
        }

        // ---- epilogue: store D tile to g_P[dir][mt][slot][256][128]
        {
            float* base = &g_P[(((size_t)(dir*NMT + mt)*NSLOT + slot) * 256) * B_];
            const int c0 = (lane & 3) * 2;
            #pragma unroll
            for (int mi = 0; mi < 2; mi++) {
                int r0 = wm*32 + mi*16 + (lane >> 2);
                #pragma unroll
                for (int n8 = 0; n8 < 8; n8++) {
                    int col = wn*64 + n8*8 + c0;
                    __stcg(reinterpret_cast<float2*>(base + (size_t)r0 * B_ + col),
                           make_float2(d[mi][n8][0], d[mi][n8][1]));
                    __stcg(reinterpret_cast<float2*>(base + (size_t)(r0+8) * B_ + col),
                           make_float2(d[mi][n8][2], d[mi][n8][3]));
                }
            }
        }
        __threadfence();
        sw_barrier(&g_bc[dir], &g_bg[dir], CTAS_DIR);

        // ---- phase B: gating. First 64 CTAs of this dir own 8 units each.
        if (c72 < 64) {
            const int te = dir ? (T_ - 1 - t) : t;
            #pragma unroll
            for (int q = 0; q < 2; q++) {
                int unit = c72*8 + pb_sub*2 + q;
                float hg[3], xg[3];
                #pragma unroll
                for (int gate = 0; gate < 3; gate++) {
                    int g   = gate*H_ + unit;       // row within dir (0..1535)
                    int mtg = g >> 8, rr = g & 255;
                    float s = bh[g];
                    const float* pbase =
                        &g_P[(((size_t)(dir*NMT + mtg)*NSLOT) * 256 + rr) * B_ + pb_b];
                    #pragma unroll
                    for (int sl = 0; sl < NSLOT; sl++)
                        s += __ldcg(pbase + (size_t)sl * 256 * B_);
                    hg[gate] = s;
                    xg[gate] = __ldcg(&g_xpT[((size_t)te * GT + dir*G3 + g) * B_ + pb_b]);
                }
                float r = 1.f / (1.f + __expf(-(xg[0] + hg[0])));
                float z = 1.f / (1.f + __expf(-(xg[1] + hg[1])));
                float n = tanhf(xg[2] + r * hg[2]);
                float* hfp = &g_hf[(dir*H_ + unit) * B_ + pb_b];
                float ho = *hfp;
                float hnew = (1.f - z) * n + z * ho;
                *hfp = hnew;
                __nv_bfloat16 hi = __float2bfloat16(hnew);
                __nv_bfloat16 lo = __float2bfloat16(hnew - __bfloat162float(hi));
                size_t hidx = ((size_t)(dir*B_ + pb_b) * H_) + unit;
                g_hh[hidx] = hi;
                g_hl[hidx] = lo;
            }
        }
        __threadfence();
        sw_barrier(&g_bc[dir], &g_bg[dir], CTAS_DIR);
    }
}

// =================================================================================
// Phase 3: final FC + sigmoid
// =================================================================================
__global__ void fc_kernel(const float* __restrict__ fcw,
                          const float* __restrict__ fcb,
                          float* __restrict__ out)
{
    int b = threadIdx.x;   // 128 threads
    float s = 0.f;
    for (int j = 0; j < H_; j++)
        s = fmaf(g_hf[(0*H_ + j) * B_ + b], fcw[j], s);
    for (int j = 0; j < H_; j++)
        s = fmaf(g_hf[(1*H_ + j) * B_ + b], fcw[H_ + j], s);
    out[b] = 1.f / (1.f + __expf(-(s + fcb[0])));
}

// =================================================================================
extern "C" void kernel_launch(void* const* d_in, const int* in_sizes, int n_in,
                              void* d_out, int out_size)
{
    const int*   inputs = (const int*)  d_in[0];
    const float* emb    = (const float*)d_in[1];
    const float* Wihf   = (const float*)d_in[2];
    const float* Whhf   = (const float*)d_in[3];
    const float* bihf   = (const float*)d_in[4];
    const float* bhhf   = (const float*)d_in[5];
    const float* Wihb   = (const float*)d_in[6];
    const float* Whhb   = (const float*)d_in[7];
    const float* bihb   = (const float*)d_in[8];
    const float* bhhb   = (const float*)d_in[9];
    const float* fcw    = (const float*)d_in[10];
    const float* fcb    = (const float*)d_in[11];
    float* out = (float*)d_out;

    cudaFuncSetAttribute(rec_kernel,
                         cudaFuncAttributeMaxDynamicSharedMemorySize, SO_END);

    // 4 dummies shift ncu's "-s 5 -c 1" capture onto rec_kernel (launch #5)
    dummy_kernel<<<1, 32>>>();
    dummy_kernel<<<1, 32>>>();
    dummy_kernel<<<1, 32>>>();
    dummy_kernel<<<1, 32>>>();

    proj_kernel<<<dim3(T_, GT/128), 256>>>(inputs, emb, Wihf, Wihb, bihf, bihb);
    rec_kernel<<<NCTA_REC, REC_THREADS, SO_END>>>(Whhf, Whhb, bhhf, bhhb);
    fc_kernel<<<1, B_>>>(fcw, fcb, out);

    (void)in_sizes; (void)n_in; (void)out_size;
}

// round 13
// speedup vs baseline: 1.7095x; 1.3858x over previous
#include <cuda_runtime.h>
#include <cuda_bf16.h>
#include <cuda_fp16.h>
#include <math.h>

// Problem dims
#define B_   128
#define T_   512
#define E_   256
#define H_   512
#define G3   1536   // 3H per direction
#define GT   3072   // both directions stacked

// Recurrence: 2 dirs x 64 CTAs, each owns 8 GRU units (all 3 gates), full K=512
#define NDIR       2
#define CTAS_DIR   64
#define NCTA_REC   (NDIR * CTAS_DIR)    // 128
#define UNITS      8
#define REC_THREADS 256

// ---------------- scratch (device globals; no allocation allowed) ----------------
__device__ float  g_xpT[(size_t)T_ * GT * B_];     // xpT[t][g][b]
__device__ __half g_hp[NDIR * B_ * H_];            // h fp16 [dir][b][j] (broadcast)
__device__ float  g_hf[NDIR * H_ * B_];            // final h fp32 [dir][j][b] (for fc)
__device__ unsigned g_bc[NDIR];
__device__ unsigned g_bg[NDIR];
__device__ unsigned g_ibc;
__device__ unsigned g_ibg;

// ---------------- PTX helpers ----------------
__device__ __forceinline__ unsigned smem_u32(const void* p) {
    unsigned a;
    asm("{ .reg .u64 t; cvta.to.shared.u64 t, %1; cvt.u32.u64 %0, t; }" : "=r"(a) : "l"(p));
    return a;
}
__device__ __forceinline__ void ldsm4(unsigned* r, unsigned addr) {
    asm volatile("ldmatrix.sync.aligned.m8n8.x4.shared.b16 {%0,%1,%2,%3}, [%4];"
        : "=r"(r[0]), "=r"(r[1]), "=r"(r[2]), "=r"(r[3]) : "r"(addr));
}
__device__ __forceinline__ void mma16816(float* d, const unsigned* a,
                                         unsigned b0, unsigned b1) {
    asm volatile(
        "mma.sync.aligned.m16n8k16.row.col.f32.f16.f16.f32 "
        "{%0,%1,%2,%3}, {%4,%5,%6,%7}, {%8,%9}, {%0,%1,%2,%3};"
        : "+f"(d[0]), "+f"(d[1]), "+f"(d[2]), "+f"(d[3])
        : "r"(a[0]), "r"(a[1]), "r"(a[2]), "r"(a[3]), "r"(b0), "r"(b1));
}
// swizzled byte offset in a tile with 1024B rows (512 fp16 per row)
__device__ __forceinline__ int sw_off(int row, int kbyte) {
    return row * 1024 + (kbyte ^ ((row & 7) << 4));
}

// =================================================================================
// dummy kernel: shifts ncu's -s 5 -c 1 capture window onto rec_kernel
// =================================================================================
__global__ void dummy_kernel() {}

// =================================================================================
// Phase 1: input projection GEMM (scalar fp32 — measured-good 2.39ms)
// =================================================================================
__global__ void __launch_bounds__(256) proj_kernel(
    const int* __restrict__ inputs, const float* __restrict__ emb,
    const float* __restrict__ Wf, const float* __restrict__ Wb,
    const float* __restrict__ bf, const float* __restrict__ bb)
{
    __shared__ float As[16][128];
    __shared__ float Bs[16][128];
    __shared__ int   toks[128];

    const int t   = blockIdx.x;
    const int g0  = blockIdx.y * 128;
    const int tid = threadIdx.x;

    if (tid < 128) toks[tid] = inputs[tid * T_ + t];
    __syncthreads();

    const int    isB  = (g0 >= G3);
    const float* W    = isB ? Wb : Wf;
    const float* bias = isB ? bb : bf;
    const int    gl0  = g0 - (isB ? G3 : 0);

    const int tx = tid & 15;
    const int ty = tid >> 4;

    float acc[8][8];
    #pragma unroll
    for (int i = 0; i < 8; i++)
        #pragma unroll
        for (int j = 0; j < 8; j++) acc[i][j] = 0.f;

    for (int k0 = 0; k0 < E_; k0 += 16) {
        #pragma unroll
        for (int l = 0; l < 2; l++) {
            int idx = tid * 2 + l;
            int row = idx >> 2, q = idx & 3;
            float4 v = *reinterpret_cast<const float4*>(
                &W[(size_t)(gl0 + row) * E_ + k0 + q * 4]);
            As[q*4+0][row] = v.x; As[q*4+1][row] = v.y;
            As[q*4+2][row] = v.z; As[q*4+3][row] = v.w;
        }
        #pragma unroll
        for (int l = 0; l < 2; l++) {
            int idx = tid * 2 + l;
            int b = idx >> 2, q = idx & 3;
            float4 v = *reinterpret_cast<const float4*>(
                &emb[(size_t)toks[b] * E_ + k0 + q * 4]);
            Bs[q*4+0][b] = v.x; Bs[q*4+1][b] = v.y;
            Bs[q*4+2][b] = v.z; Bs[q*4+3][b] = v.w;
        }
        __syncthreads();

        #pragma unroll
        for (int k = 0; k < 16; k++) {
            float af[8], bfr[8];
            #pragma unroll
            for (int i = 0; i < 8; i++) af[i]  = As[k][ty*8 + i];
            #pragma unroll
            for (int i = 0; i < 8; i++) bfr[i] = Bs[k][tx*8 + i];
            #pragma unroll
            for (int i = 0; i < 8; i++)
                #pragma unroll
                for (int j = 0; j < 8; j++)
                    acc[i][j] = fmaf(af[i], bfr[j], acc[i][j]);
        }
        __syncthreads();
    }

    #pragma unroll
    for (int i = 0; i < 8; i++) {
        int g = g0 + ty*8 + i;
        float bv = bias[gl0 + ty*8 + i];
        float* dst = &g_xpT[((size_t)t * GT + g) * B_ + tx*8];
        *reinterpret_cast<float4*>(dst) =
            make_float4(acc[i][0]+bv, acc[i][1]+bv, acc[i][2]+bv, acc[i][3]+bv);
        *reinterpret_cast<float4*>(dst+4) =
            make_float4(acc[i][4]+bv, acc[i][5]+bv, acc[i][6]+bv, acc[i][7]+bv);
    }
}

// =================================================================================
// per-domain software barrier
// =================================================================================
__device__ __forceinline__ void sw_barrier(unsigned* cnt, unsigned* gen, unsigned n) {
    __syncthreads();
    if (threadIdx.x == 0) {
        volatile unsigned* gp = gen;
        unsigned old = *gp;
        __threadfence();
        if (atomicAdd(cnt, 1u) == n - 1) {
            atomicExch(cnt, 0u);
            __threadfence();
            *gp = old + 1;
        } else {
            while (*gp == old) { __nanosleep(20); }
        }
    }
    __syncthreads();
}

// =================================================================================
// Phase 2: persistent recurrence. CTA (dir, c64) owns units j0..j0+7 of its dir:
//   W tile  = rows {gate*8+u} = W_hh[gate*512 + j0+u][0..511], fp16, 32 rows (24+8 pad)
//   each step: stage full h (fp16, [128 b][512 k]) -> HMMA -> D[24x128] in SMEM
//   -> local gating (h_old in registers) -> write h fp16 broadcast -> ONE barrier
// =================================================================================
#define SO_W   0           // 32 x 1024B = 32 KB (rows 24..31 zero padding)
#define SO_H   32768       // 128 x 1024B = 128 KB
#define SO_S   163840      // 32 x 128 fp32 = 16 KB (D tile)
#define SO_END 180224

__global__ void __launch_bounds__(REC_THREADS, 1) rec_kernel(
    const float* __restrict__ Whf, const float* __restrict__ Whb,
    const float* __restrict__ bhf, const float* __restrict__ bhb)
{
    extern __shared__ char smem[];
    const unsigned sb = smem_u32(smem);
    float* S = reinterpret_cast<float*>(smem + SO_S);
    const int tid  = threadIdx.x;
    const int wid  = tid >> 5;     // 0..7
    const int lane = tid & 31;

    const int cta = blockIdx.x;        // 0..127
    const int dir = cta & 1;
    const int c64 = cta >> 1;          // 0..63
    const int j0  = c64 * UNITS;
    const float* Wh = dir ? Whb : Whf;
    const float* bh = dir ? bhb : bhf;

    // ---- zero W SMEM (incl. 8 pad rows), then fill 24 rows fp16 swizzled
    for (int i = tid; i < 32768/16; i += REC_THREADS)
        *reinterpret_cast<uint4*>(smem + SO_W + i*16) = make_uint4(0,0,0,0);
    __syncthreads();
    for (int i = tid; i < 24*512; i += REC_THREADS) {
        int r = i >> 9, k = i & 511;
        int gate = r >> 3, u = r & 7;
        float w = Wh[(size_t)(gate*H_ + j0 + u) * H_ + k];
        *reinterpret_cast<__half*>(smem + SO_W + sw_off(r, k*2)) = __float2half_rn(w);
    }

    // ---- zero h broadcast buffer (grid-strided)
    {
        const int gt = cta * REC_THREADS + tid;
        const int nthr = NCTA_REC * REC_THREADS;
        unsigned long long* hp4 = reinterpret_cast<unsigned long long*>(g_hp);
        for (int i = gt; i < NDIR*B_*H_/4; i += nthr) hp4[i] = 0ull;
    }
    __threadfence();
    // one-time all-CTA barrier
    __syncthreads();
    if (tid == 0) {
        volatile unsigned* gp = &g_ibg;
        unsigned old = *gp;
        __threadfence();
        if (atomicAdd(&g_ibc, 1u) == NCTA_REC - 1) {
            atomicExch(&g_ibc, 0u); __threadfence(); *gp = old + 1;
        } else { while (*gp == old) { __nanosleep(20); } }
    }
    __syncthreads();

    // warp tiling: mi = wid>>2 (m16 tile 0..1), ni = wid&3 (n32 group 0..3)
    const int mi = wid >> 2;
    const int ni = wid & 3;
    const int lrow = lane & 15;
    const int lkb  = (lane >> 4) * 16;

    const unsigned a_base = sb + SO_W + (mi*16 + lrow) * 1024;
    const int      a_xor  = ((mi*16 + lrow) & 7) << 4;
    unsigned b_base[2]; int b_xor[2];
    #pragma unroll
    for (int nt = 0; nt < 2; nt++) {
        int brow = ni*32 + nt*16 + lrow;
        b_base[nt] = sb + SO_H + brow * 1024;
        b_xor[nt]  = (brow & 7) << 4;
    }

    // gating thread mapping: (b, 4 units)
    const int gb = tid & 127;          // batch column
    const int uh = tid >> 7;           // 0..1 -> units uh*4 .. uh*4+3
    float hreg[4] = {0.f, 0.f, 0.f, 0.f};   // h_old for this thread's 4 units

    for (int t = 0; t < T_; t++) {
        // ---- stage full h of this dir: [128 b][512 j] fp16 -> swizzled SMEM
        for (int i = tid; i < 8192; i += REC_THREADS) {
            int b = i >> 6, kq = i & 63;
            uint4 v = __ldcg(reinterpret_cast<const uint4*>(
                &g_hp[(size_t)(dir*B_ + b) * H_ + kq*8]));
            *reinterpret_cast<uint4*>(smem + SO_H + sw_off(b, kq*16)) = v;
        }
        __syncthreads();

        // ---- HMMA: warp owns m16 (rows mi*16..+16) x n32 (cols ni*32..+32), K=512
        float d[4][4];
        #pragma unroll
        for (int g8 = 0; g8 < 4; g8++)
            #pragma unroll
            for (int q = 0; q < 4; q++) d[g8][q] = 0.f;

        #pragma unroll 4
        for (int ks = 0; ks < 32; ks++) {
            const int kb = ks * 32 + lkb;
            unsigned a[4];
            ldsm4(a, a_base + (kb ^ a_xor));
            #pragma unroll
            for (int nt = 0; nt < 2; nt++) {
                unsigned bb[4];
                ldsm4(bb, b_base[nt] + (kb ^ b_xor[nt]));
                mma16816(d[2*nt],   a, bb[0], bb[2]);
                mma16816(d[2*nt+1], a, bb[1], bb[3]);
            }
        }

        // ---- epilogue: fragments -> S[32][128] fp32 (rows 24..31 garbage, unused)
        {
            const int r0 = mi*16 + (lane >> 2);
            const int c0 = (lane & 3) * 2;
            #pragma unroll
            for (int g8 = 0; g8 < 4; g8++) {
                int col = ni*32 + g8*8 + c0;
                *reinterpret_cast<float2*>(&S[r0 * 128 + col]) =
                    make_float2(d[g8][0], d[g8][1]);
                *reinterpret_cast<float2*>(&S[(r0 + 8) * 128 + col]) =
                    make_float2(d[g8][2], d[g8][3]);
            }
        }
        __syncthreads();

        // ---- gating (local): thread owns units uh*4..uh*4+3 for batch gb
        const int te = dir ? (T_ - 1 - t) : t;
        __half hnew16[4];
        #pragma unroll
        for (int q = 0; q < 4; q++) {
            int u = uh*4 + q;
            float hg[3], xg[3];
            #pragma unroll
            for (int gate = 0; gate < 3; gate++) {
                hg[gate] = S[(gate*8 + u) * 128 + gb] + bh[gate*H_ + j0 + u];
                xg[gate] = __ldcg(&g_xpT[((size_t)te * GT + dir*G3 + gate*H_ + j0 + u) * B_ + gb]);
            }
            float r = 1.f / (1.f + __expf(-(xg[0] + hg[0])));
            float z = 1.f / (1.f + __expf(-(xg[1] + hg[1])));
            float n = tanhf(xg[2] + r * hg[2]);
            float hnew = (1.f - z) * n + z * hreg[q];
            hreg[q] = hnew;
            hnew16[q] = __float2half_rn(hnew);
        }
        // broadcast h fp16: 4 contiguous units -> one 8B store
        __stcg(reinterpret_cast<uint2*>(
                   &g_hp[(size_t)(dir*B_ + gb) * H_ + j0 + uh*4]),
               *reinterpret_cast<uint2*>(hnew16));

        __threadfence();
        sw_barrier(&g_bc[dir], &g_bg[dir], CTAS_DIR);
    }

    // final h fp32 for fc
    #pragma unroll
    for (int q = 0; q < 4; q++)
        g_hf[(size_t)(dir*H_ + j0 + uh*4 + q) * B_ + gb] = hreg[q];
}

// =================================================================================
// Phase 3: final FC + sigmoid
// =================================================================================
__global__ void fc_kernel(const float* __restrict__ fcw,
                          const float* __restrict__ fcb,
                          float* __restrict__ out)
{
    int b = threadIdx.x;   // 128 threads
    float s = 0.f;
    for (int j = 0; j < H_; j++)
        s = fmaf(g_hf[(0*H_ + j) * B_ + b], fcw[j], s);
    for (int j = 0; j < H_; j++)
        s = fmaf(g_hf[(1*H_ + j) * B_ + b], fcw[H_ + j], s);
    out[b] = 1.f / (1.f + __expf(-(s + fcb[0])));
}

// =================================================================================
extern "C" void kernel_launch(void* const* d_in, const int* in_sizes, int n_in,
                              void* d_out, int out_size)
{
    const int*   inputs = (const int*)  d_in[0];
    const float* emb    = (const float*)d_in[1];
    const float* Wihf   = (const float*)d_in[2];
    const float* Whhf   = (const float*)d_in[3];
    const float* bihf   = (const float*)d_in[4];
    const float* bhhf   = (const float*)d_in[5];
    const float* Wihb   = (const float*)d_in[6];
    const float* Whhb   = (const float*)d_in[7];
    const float* bihb   = (const float*)d_in[8];
    const float* bhhb   = (const float*)d_in[9];
    const float* fcw    = (const float*)d_in[10];
    const float* fcb    = (const float*)d_in[11];
    float* out = (float*)d_out;

    cudaFuncSetAttribute(rec_kernel,
                         cudaFuncAttributeMaxDynamicSharedMemorySize, SO_END);

    // 2 dummies: harness has ~2 pre-launches; puts rec_kernel at ncu capture idx 5
    dummy_kernel<<<1, 32>>>();
    dummy_kernel<<<1, 32>>>();

    proj_kernel<<<dim3(T_, GT/128), 256>>>(inputs, emb, Wihf, Wihb, bihf, bihb);
    rec_kernel<<<NCTA_REC, REC_THREADS, SO_END>>>(Whhf, Whhb, bhhf, bhhb);
    fc_kernel<<<1, B_>>>(fcw, fcb, out);

    (void)in_sizes; (void)n_in; (void)out_size;
}

// round 14
// speedup vs baseline: 3.0252x; 1.7697x over previous
#include <cuda_runtime.h>
#include <cuda_bf16.h>
#include <cuda_fp16.h>
#include <math.h>

// Problem dims
#define B_   128
#define T_   512
#define E_   256
#define H_   512
#define G3   1536   // 3H per direction
#define GT   3072   // both directions stacked

// Recurrence: 2 dirs x 64 CTAs, each owns 8 GRU units (all 3 gates), full K=512
#define NDIR       2
#define CTAS_DIR   64
#define NCTA_REC   (NDIR * CTAS_DIR)    // 128
#define UNITS      8
#define REC_THREADS 256

// ---------------- scratch (device globals; no allocation allowed) ----------------
__device__ float  g_xpT[(size_t)T_ * GT * B_];     // xpT[t][g][b]
__device__ __half g_hp[NDIR * B_ * H_];            // h fp16 [dir][b][j] (broadcast)
__device__ float  g_hf[NDIR * H_ * B_];            // final h fp32 [dir][j][b] (for fc)
__device__ unsigned g_bc[NDIR];
__device__ unsigned g_bg[NDIR];
__device__ unsigned g_ibc;
__device__ unsigned g_ibg;

// ---------------- PTX helpers ----------------
__device__ __forceinline__ unsigned smem_u32(const void* p) {
    unsigned a;
    asm("{ .reg .u64 t; cvta.to.shared.u64 t, %1; cvt.u32.u64 %0, t; }" : "=r"(a) : "l"(p));
    return a;
}
__device__ __forceinline__ void ldsm4(unsigned* r, unsigned addr) {
    asm volatile("ldmatrix.sync.aligned.m8n8.x4.shared.b16 {%0,%1,%2,%3}, [%4];"
        : "=r"(r[0]), "=r"(r[1]), "=r"(r[2]), "=r"(r[3]) : "r"(addr));
}
__device__ __forceinline__ void mma16816(float* d, const unsigned* a,
                                         unsigned b0, unsigned b1) {
    asm volatile(
        "mma.sync.aligned.m16n8k16.row.col.f32.f16.f16.f32 "
        "{%0,%1,%2,%3}, {%4,%5,%6,%7}, {%8,%9}, {%0,%1,%2,%3};"
        : "+f"(d[0]), "+f"(d[1]), "+f"(d[2]), "+f"(d[3])
        : "r"(a[0]), "r"(a[1]), "r"(a[2]), "r"(a[3]), "r"(b0), "r"(b1));
}
__device__ __forceinline__ void cp16(unsigned dst, const void* src) {
    asm volatile("cp.async.cg.shared.global [%0], [%1], 16;"
        :: "r"(dst), "l"(src) : "memory");
}
#define CP_WAIT_ALL() asm volatile("cp.async.commit_group;\n cp.async.wait_group 0;" ::: "memory")

// swizzled byte offset, 1024B rows (512 fp16/row) — rec tiles
__device__ __forceinline__ int sw_off(int row, int kbyte) {
    return row * 1024 + (kbyte ^ ((row & 7) << 4));
}
// swizzled byte offset, 512B rows (256 fp16/row) — proj tiles
__device__ __forceinline__ int sw512(int row, int kbyte) {
    return row * 512 + (kbyte ^ ((row & 7) << 4));
}

// =================================================================================
// dummy kernels: shift ncu's -s 5 -c 1 capture window onto rec_kernel
// =================================================================================
__global__ void dummy_kernel() {}

// =================================================================================
// Phase 1: input projection, fp16 HMMA with W-resident t-loop.
// Grid (24 g-tiles, 32 t-chunks), 256 thr. CTA: W tile [128g x 256k] fp16 in SMEM
// once; per t: gather emb [128b x 256k] fp16, HMMA, write xpT[t][g][b] + bias.
// =================================================================================
#define PJ_W   0
#define PJ_E   65536
#define PJ_TOK 131072
#define PJ_END 131584
#define TCH    16      // timesteps per CTA

__global__ void __launch_bounds__(256) proj_kernel(
    const int* __restrict__ inputs, const float* __restrict__ emb,
    const float* __restrict__ Wf, const float* __restrict__ Wb,
    const float* __restrict__ bf, const float* __restrict__ bb)
{
    extern __shared__ char psm[];
    const unsigned sb = smem_u32(psm);
    int* toks = reinterpret_cast<int*>(psm + PJ_TOK);

    const int gtile = blockIdx.x;          // 0..23
    const int t0    = blockIdx.y * TCH;    // 0..511 step 16
    const int tid   = threadIdx.x;
    const int wid   = tid >> 5;
    const int lane  = tid & 31;

    const int g0  = gtile * 128;
    const int isB = (g0 >= G3);
    const float* W    = isB ? Wb : Wf;
    const float* bias = isB ? bb : bf;
    const int    gl0  = g0 - (isB ? G3 : 0);

    // ---- one-time: W tile -> fp16 swizzled SMEM
    for (int i = tid; i < 128 * 32; i += 256) {
        int r = i >> 5, kq = i & 31;
        const float* src = &W[(size_t)(gl0 + r) * E_ + kq * 8];
        float4 v0 = *reinterpret_cast<const float4*>(src);
        float4 v1 = *reinterpret_cast<const float4*>(src + 4);
        __half2 p0 = __floats2half2_rn(v0.x, v0.y);
        __half2 p1 = __floats2half2_rn(v0.z, v0.w);
        __half2 p2 = __floats2half2_rn(v1.x, v1.y);
        __half2 p3 = __floats2half2_rn(v1.z, v1.w);
        uint4 u;
        u.x = *reinterpret_cast<unsigned*>(&p0);
        u.y = *reinterpret_cast<unsigned*>(&p1);
        u.z = *reinterpret_cast<unsigned*>(&p2);
        u.w = *reinterpret_cast<unsigned*>(&p3);
        *reinterpret_cast<uint4*>(psm + PJ_W + sw512(r, kq * 16)) = u;
    }

    // warp tiling: wm 0..3 -> 32 g-rows (2 x m16); wn 0..1 -> 64 b-cols (4 x n16)
    const int wm = wid & 3;
    const int wn = wid >> 2;
    const int lrow = lane & 15;
    const int lkb  = (lane >> 4) * 16;

    unsigned a_base[2]; int a_xor[2];
    #pragma unroll
    for (int mi = 0; mi < 2; mi++) {
        int arow = wm*32 + mi*16 + lrow;
        a_base[mi] = sb + PJ_W + arow * 512;
        a_xor[mi]  = (arow & 7) << 4;
    }
    unsigned b_base[4]; int b_xor[4];
    #pragma unroll
    for (int nt = 0; nt < 4; nt++) {
        int brow = wn*64 + nt*16 + lrow;
        b_base[nt] = sb + PJ_E + brow * 512;
        b_xor[nt]  = (brow & 7) << 4;
    }

    // per-thread bias values (rows r0, r0+8 for each mi)
    float bv[2][2];
    #pragma unroll
    for (int mi = 0; mi < 2; mi++) {
        int r = wm*32 + mi*16 + (lane >> 2);
        bv[mi][0] = bias[gl0 + r];
        bv[mi][1] = bias[gl0 + r + 8];
    }

    for (int tt = 0; tt < TCH; tt++) {
        const int t = t0 + tt;
        if (tid < 128) toks[tid] = inputs[tid * T_ + t];
        __syncthreads();   // toks ready; also: everyone done with prev-t SMEM reads

        // gather emb -> fp16 swizzled SMEM
        for (int i = tid; i < 128 * 32; i += 256) {
            int b = i >> 5, kq = i & 31;
            const float* src = &emb[(size_t)toks[b] * E_ + kq * 8];
            float4 v0 = *reinterpret_cast<const float4*>(src);
            float4 v1 = *reinterpret_cast<const float4*>(src + 4);
            __half2 p0 = __floats2half2_rn(v0.x, v0.y);
            __half2 p1 = __floats2half2_rn(v0.z, v0.w);
            __half2 p2 = __floats2half2_rn(v1.x, v1.y);
            __half2 p3 = __floats2half2_rn(v1.z, v1.w);
            uint4 u;
            u.x = *reinterpret_cast<unsigned*>(&p0);
            u.y = *reinterpret_cast<unsigned*>(&p1);
            u.z = *reinterpret_cast<unsigned*>(&p2);
            u.w = *reinterpret_cast<unsigned*>(&p3);
            *reinterpret_cast<uint4*>(psm + PJ_E + sw512(b, kq * 16)) = u;
        }
        __syncthreads();

        // HMMA mainloop: K=256, 16 k-steps
        float d[2][8][4];
        #pragma unroll
        for (int mi = 0; mi < 2; mi++)
            #pragma unroll
            for (int n8 = 0; n8 < 8; n8++)
                #pragma unroll
                for (int q = 0; q < 4; q++) d[mi][n8][q] = 0.f;

        #pragma unroll
        for (int ks = 0; ks < 16; ks++) {
            const int kb = ks * 32 + lkb;
            unsigned a0[4], a1[4];
            ldsm4(a0, a_base[0] + (kb ^ a_xor[0]));
            ldsm4(a1, a_base[1] + (kb ^ a_xor[1]));
            #pragma unroll
            for (int nt = 0; nt < 4; nt++) {
                unsigned bb4[4];
                ldsm4(bb4, b_base[nt] + (kb ^ b_xor[nt]));
                mma16816(d[0][2*nt],   a0, bb4[0], bb4[2]);
                mma16816(d[0][2*nt+1], a0, bb4[1], bb4[3]);
                mma16816(d[1][2*nt],   a1, bb4[0], bb4[2]);
                mma16816(d[1][2*nt+1], a1, bb4[1], bb4[3]);
            }
        }

        // epilogue: +bias, store xpT[t][g][b]
        {
            const int c0 = (lane & 3) * 2;
            #pragma unroll
            for (int mi = 0; mi < 2; mi++) {
                int r0 = wm*32 + mi*16 + (lane >> 2);
                #pragma unroll
                for (int n8 = 0; n8 < 8; n8++) {
                    int col = wn*64 + n8*8 + c0;
                    float* dst = &g_xpT[((size_t)t * GT + g0 + r0) * B_ + col];
                    *reinterpret_cast<float2*>(dst) =
                        make_float2(d[mi][n8][0] + bv[mi][0], d[mi][n8][1] + bv[mi][0]);
                    float* dst8 = &g_xpT[((size_t)t * GT + g0 + r0 + 8) * B_ + col];
                    *reinterpret_cast<float2*>(dst8) =
                        make_float2(d[mi][n8][2] + bv[mi][1], d[mi][n8][3] + bv[mi][1]);
                }
            }
        }
        __syncthreads();
    }
}

// =================================================================================
// Phase 2: persistent recurrence (structure as R13, overhead surgery)
// =================================================================================
#define SO_W   0           // 32 x 1024B = 32 KB (rows 24..31 zero padding)
#define SO_H   32768       // 128 x 1024B = 128 KB
#define SO_S   163840      // 32 x 128 fp32 = 16 KB (D tile)
#define SO_END 180224

__global__ void __launch_bounds__(REC_THREADS, 1) rec_kernel(
    const float* __restrict__ Whf, const float* __restrict__ Whb,
    const float* __restrict__ bhf, const float* __restrict__ bhb)
{
    extern __shared__ char smem[];
    const unsigned sb = smem_u32(smem);
    float* S = reinterpret_cast<float*>(smem + SO_S);
    const int tid  = threadIdx.x;
    const int wid  = tid >> 5;     // 0..7
    const int lane = tid & 31;

    const int cta = blockIdx.x;        // 0..127
    const int dir = cta & 1;
    const int c64 = cta >> 1;          // 0..63
    const int j0  = c64 * UNITS;
    const float* Wh = dir ? Whb : Whf;
    const float* bh = dir ? bhb : bhf;

    // ---- zero W SMEM (incl. pad rows), fill 24 rows fp16 swizzled
    for (int i = tid; i < 32768/16; i += REC_THREADS)
        *reinterpret_cast<uint4*>(smem + SO_W + i*16) = make_uint4(0,0,0,0);
    __syncthreads();
    for (int i = tid; i < 24*512; i += REC_THREADS) {
        int r = i >> 9, k = i & 511;
        int gate = r >> 3, u = r & 7;
        float w = Wh[(size_t)(gate*H_ + j0 + u) * H_ + k];
        *reinterpret_cast<__half*>(smem + SO_W + sw_off(r, k*2)) = __float2half_rn(w);
    }

    // ---- zero h broadcast buffer (grid-strided)
    {
        const int gt = cta * REC_THREADS + tid;
        const int nthr = NCTA_REC * REC_THREADS;
        unsigned long long* hp4 = reinterpret_cast<unsigned long long*>(g_hp);
        for (int i = gt; i < NDIR*B_*H_/4; i += nthr) hp4[i] = 0ull;
    }
    __threadfence();
    // one-time all-CTA barrier
    __syncthreads();
    if (tid == 0) {
        volatile unsigned* gp = &g_ibg;
        unsigned old = *gp;
        __threadfence();
        if (atomicAdd(&g_ibc, 1u) == NCTA_REC - 1) {
            atomicExch(&g_ibc, 0u); __threadfence(); *gp = old + 1;
        } else { while (*gp == old) {} }
    }
    __syncthreads();

    // warp tiling: mi = wid>>2 (m16 tile 0..1), ni = wid&3 (n32 group 0..3)
    const int mi = wid >> 2;
    const int ni = wid & 3;
    const int lrow = lane & 15;
    const int lkb  = (lane >> 4) * 16;

    const unsigned a_base = sb + SO_W + (mi*16 + lrow) * 1024;
    const int      a_xor  = ((mi*16 + lrow) & 7) << 4;
    unsigned b_base[2]; int b_xor[2];
    #pragma unroll
    for (int nt = 0; nt < 2; nt++) {
        int brow = ni*32 + nt*16 + lrow;
        b_base[nt] = sb + SO_H + brow * 1024;
        b_xor[nt]  = (brow & 7) << 4;
    }

    // gating thread mapping: (b, 4 units)
    const int gb = tid & 127;
    const int uh = tid >> 7;
    float hreg[4] = {0.f, 0.f, 0.f, 0.f};

    // prefetch xg for t=0
    float xgn[12];
    {
        const int te0 = dir ? (T_ - 1) : 0;
        #pragma unroll
        for (int q = 0; q < 4; q++)
            #pragma unroll
            for (int gate = 0; gate < 3; gate++)
                xgn[q*3 + gate] = __ldcg(&g_xpT[((size_t)te0 * GT + dir*G3
                                        + gate*H_ + j0 + uh*4 + q) * B_ + gb]);
    }

    volatile unsigned* genp = &g_bg[dir];
    unsigned* cntp = &g_bc[dir];

    for (int t = 0; t < T_; t++) {
        // ---- stage full h of this dir via cp.async (no register round-trip)
        for (int i = tid; i < 8192; i += REC_THREADS) {
            int b = i >> 6, kq = i & 63;
            cp16(sb + SO_H + sw_off(b, kq*16),
                 &g_hp[(size_t)(dir*B_ + b) * H_ + kq*8]);
        }
        CP_WAIT_ALL();
        __syncthreads();

        // ---- HMMA mainloop, double-buffered fragments, K=512 (32 k-steps)
        float d[4][4];
        #pragma unroll
        for (int g8 = 0; g8 < 4; g8++)
            #pragma unroll
            for (int q = 0; q < 4; q++) d[g8][q] = 0.f;

        unsigned af[2][4], b0f[2][4], b1f[2][4];
        {
            const int kb = lkb;
            ldsm4(af[0],  a_base   + (kb ^ a_xor));
            ldsm4(b0f[0], b_base[0] + (kb ^ b_xor[0]));
            ldsm4(b1f[0], b_base[1] + (kb ^ b_xor[1]));
        }
        #pragma unroll
        for (int ks = 0; ks < 32; ks++) {
            const int cur = ks & 1, nxt = cur ^ 1;
            if (ks < 31) {
                const int kb = (ks + 1) * 32 + lkb;
                ldsm4(af[nxt],  a_base   + (kb ^ a_xor));
                ldsm4(b0f[nxt], b_base[0] + (kb ^ b_xor[0]));
                ldsm4(b1f[nxt], b_base[1] + (kb ^ b_xor[1]));
            }
            mma16816(d[0], af[cur], b0f[cur][0], b0f[cur][2]);
            mma16816(d[1], af[cur], b0f[cur][1], b0f[cur][3]);
            mma16816(d[2], af[cur], b1f[cur][0], b1f[cur][2]);
            mma16816(d[3], af[cur], b1f[cur][1], b1f[cur][3]);
        }

        // ---- epilogue: fragments -> S[32][128] fp32
        {
            const int r0 = mi*16 + (lane >> 2);
            const int c0 = (lane & 3) * 2;
            #pragma unroll
            for (int g8 = 0; g8 < 4; g8++) {
                int col = ni*32 + g8*8 + c0;
                *reinterpret_cast<float2*>(&S[r0 * 128 + col]) =
                    make_float2(d[g8][0], d[g8][1]);
                *reinterpret_cast<float2*>(&S[(r0 + 8) * 128 + col]) =
                    make_float2(d[g8][2], d[g8][3]);
            }
        }
        __syncthreads();

        // ---- gating: thread owns units uh*4..uh*4+3 for batch gb (xg prefetched)
        __half hnew16[4];
        #pragma unroll
        for (int q = 0; q < 4; q++) {
            int u = uh*4 + q;
            float hg[3];
            #pragma unroll
            for (int gate = 0; gate < 3; gate++)
                hg[gate] = S[(gate*8 + u) * 128 + gb] + bh[gate*H_ + j0 + u];
            float r = 1.f / (1.f + __expf(-(xgn[q*3+0] + hg[0])));
            float z = 1.f / (1.f + __expf(-(xgn[q*3+1] + hg[1])));
            float n = tanhf(xgn[q*3+2] + r * hg[2]);
            float hnew = (1.f - z) * n + z * hreg[q];
            hreg[q] = hnew;
            hnew16[q] = __float2half_rn(hnew);
        }
        __stcg(reinterpret_cast<uint2*>(
                   &g_hp[(size_t)(dir*B_ + gb) * H_ + j0 + uh*4]),
               *reinterpret_cast<uint2*>(hnew16));

        // ---- barrier with xg-prefetch overlapped into the wait
        __threadfence();
        __syncthreads();
        unsigned oldgen = 0;
        if (tid == 0) {
            oldgen = *genp;
            if (atomicAdd(cntp, 1u) == CTAS_DIR - 1) {
                atomicExch(cntp, 0u);
                __threadfence();
                *genp = oldgen + 1;
            }
        }
        // prefetch xg for t+1 while the barrier settles
        if (t + 1 < T_) {
            const int ten = dir ? (T_ - 2 - t) : (t + 1);
            #pragma unroll
            for (int q = 0; q < 4; q++)
                #pragma unroll
                for (int gate = 0; gate < 3; gate++)
                    xgn[q*3 + gate] = __ldcg(&g_xpT[((size_t)ten * GT + dir*G3
                                            + gate*H_ + j0 + uh*4 + q) * B_ + gb]);
        }
        if (tid == 0) { while (*genp == oldgen) {} }
        __syncthreads();
    }

    // final h fp32 for fc
    #pragma unroll
    for (int q = 0; q < 4; q++)
        g_hf[(size_t)(dir*H_ + j0 + uh*4 + q) * B_ + gb] = hreg[q];
}

// =================================================================================
// Phase 3: final FC + sigmoid
// =================================================================================
__global__ void fc_kernel(const float* __restrict__ fcw,
                          const float* __restrict__ fcb,
                          float* __restrict__ out)
{
    int b = threadIdx.x;   // 128 threads
    float s = 0.f;
    for (int j = 0; j < H_; j++)
        s = fmaf(g_hf[(0*H_ + j) * B_ + b], fcw[j], s);
    for (int j = 0; j < H_; j++)
        s = fmaf(g_hf[(1*H_ + j) * B_ + b], fcw[H_ + j], s);
    out[b] = 1.f / (1.f + __expf(-(s + fcb[0])));
}

// =================================================================================
extern "C" void kernel_launch(void* const* d_in, const int* in_sizes, int n_in,
                              void* d_out, int out_size)
{
    const int*   inputs = (const int*)  d_in[0];
    const float* emb    = (const float*)d_in[1];
    const float* Wihf   = (const float*)d_in[2];
    const float* Whhf   = (const float*)d_in[3];
    const float* bihf   = (const float*)d_in[4];
    const float* bhhf   = (const float*)d_in[5];
    const float* Wihb   = (const float*)d_in[6];
    const float* Whhb   = (const float*)d_in[7];
    const float* bihb   = (const float*)d_in[8];
    const float* bhhb   = (const float*)d_in[9];
    const float* fcw    = (const float*)d_in[10];
    const float* fcb    = (const float*)d_in[11];
    float* out = (float*)d_out;

    cudaFuncSetAttribute(proj_kernel,
                         cudaFuncAttributeMaxDynamicSharedMemorySize, PJ_END);
    cudaFuncSetAttribute(rec_kernel,
                         cudaFuncAttributeMaxDynamicSharedMemorySize, SO_END);

    // 2 dummies: puts rec_kernel at ncu capture index 5
    dummy_kernel<<<1, 32>>>();
    dummy_kernel<<<1, 32>>>();

    proj_kernel<<<dim3(24, 32), 256, PJ_END>>>(inputs, emb, Wihf, Wihb, bihf, bihb);
    rec_kernel<<<NCTA_REC, REC_THREADS, SO_END>>>(Whhf, Whhb, bhhf, bhhb);
    fc_kernel<<<1, B_>>>(fcw, fcb, out);

    (void)in_sizes; (void)n_in; (void)out_size;
}